// round 12
// baseline (speedup 1.0000x reference)
#include <cuda_runtime.h>
#include <cstddef>

// Problem constants (fixed by the dataset)
#define BATCH 4
#define CH    32
#define HH    120
#define WW    160
#define NXc   160
#define NYc   160
#define NZc   64
#define NVOX  (NXc * NYc * NZc)     // 1,638,400
#define HW    (HH * WW)             // 19,200

#define CH_SPLIT  8                 // threads sharing one voxel-group
#define CH_PER_T  (CH / CH_SPLIT)   // 4 channels per thread

// One thread handles 4 consecutive z-voxels (z innermost / contiguous in the
// output) x 4 channels -> every per-channel store is a coalesced float4.
// Channel work is split across 8 threads per voxel-group: each split halving
// of the LDG->STG dependency chain has paid off (R7:210 -> R8:187 -> R10:160us).
// Projection is recomputed per thread (~50 FLOPs; fma/alu pipes at 14%/16%
// at split=4, so the x2 redundancy stays below any pipe bound).
// Gathers stay in the native [B,C,H,W] layout: adjacent lanes sweep nearby
// pixels within one channel plane, so scalar LDGs are warp-coherent (the R9
// [HW][C]-transpose experiment proved the transposed layout is WORSE).
//
// __launch_bounds__(256, 8) keeps regs <= 32 -> 64-warp occupancy ceiling.
//
// Projection math uses explicit IEEE-rounded intrinsics to bit-match the XLA
// reference (verified rel_err == 0.0 in R6-R10):
//   world  = coords*vs + origin          (separate mul, add — NO fma)
//   camera = sum_j P[i,j]*world[j]       (rounded products, ascending adds)
//   u      = camera_x / camera_z         (IEEE correctly-rounded divide)
//   px     = round-half-even(u)          (__float2int_rn == jnp.round)
__global__ __launch_bounds__(256, 8) void backproject_kernel(
    const float* __restrict__ origin,      // [B,3]
    const float* __restrict__ projection,  // [B,3,4]
    const float* __restrict__ features,    // [B,C,H,W]
    const float* __restrict__ voxel_size,  // [1]
    float* __restrict__ out)               // volume [B,C,NVOX] ++ valid [B,NVOX]
{
    const int groups_per_batch = NVOX / 4;             // 409,600
    int gid = blockIdx.x * blockDim.x + threadIdx.x;
    if (gid >= BATCH * CH_SPLIT * groups_per_batch) return;

    int r  = gid % groups_per_batch;          // voxel group within batch
    int bh = gid / groups_per_batch;          // b * CH_SPLIT + h
    int h  = bh % CH_SPLIT;                   // channel slice
    int b  = bh / CH_SPLIT;

    int v0 = r * 4;                 // base voxel index within batch
    int k  = v0 & (NZc - 1);        // z (NZ=64, 4-aligned chunks)
    int ij = v0 >> 6;               // i*NY + j
    int j  = ij % NYc;
    int i  = ij / NYc;

    const float vs = __ldg(voxel_size);
    const float* P = projection + b * 12;
    float P00 = __ldg(P + 0),  P01 = __ldg(P + 1),  P02 = __ldg(P + 2),  P03 = __ldg(P + 3);
    float P10 = __ldg(P + 4),  P11 = __ldg(P + 5),  P12 = __ldg(P + 6),  P13 = __ldg(P + 7);
    float P20 = __ldg(P + 8),  P21 = __ldg(P + 9),  P22 = __ldg(P + 10), P23 = __ldg(P + 11);

    float ox = __ldg(origin + b * 3 + 0);
    float oy = __ldg(origin + b * 3 + 1);
    float oz = __ldg(origin + b * 3 + 2);

    // world x/y: separately-rounded mul then add (matches coords*vs + origin)
    float wx = __fadd_rn(__fmul_rn((float)i, vs), ox);
    float wy = __fadd_rn(__fmul_rn((float)j, vs), oy);

    int  fidx[4];
    bool ok[4];
#pragma unroll
    for (int m = 0; m < 4; ++m) {
        float wz = __fadd_rn(__fmul_rn((float)(k + m), vs), oz);

        // camera_i = ((P_i0*wx + P_i1*wy) + P_i2*wz) + P_i3, each op rounded,
        // ascending j, no contraction.
        float cx = __fadd_rn(__fadd_rn(__fadd_rn(__fmul_rn(P00, wx),
                                                  __fmul_rn(P01, wy)),
                                        __fmul_rn(P02, wz)), P03);
        float cy = __fadd_rn(__fadd_rn(__fadd_rn(__fmul_rn(P10, wx),
                                                  __fmul_rn(P11, wy)),
                                        __fmul_rn(P12, wz)), P13);
        float cz = __fadd_rn(__fadd_rn(__fadd_rn(__fmul_rn(P20, wx),
                                                  __fmul_rn(P21, wy)),
                                        __fmul_rn(P22, wz)), P23);

        float u = __fdiv_rn(cx, cz);   // IEEE rn divide (immune to fast-math)
        float v = __fdiv_rn(cy, cz);
        int ipx = __float2int_rn(u);   // round-half-even == jnp.round
        int ipy = __float2int_rn(v);
        ok[m] = (ipx >= 0) && (ipy >= 0) && (ipx < WW) && (ipy < HH) && (cz > 0.0f);
        int cpx = min(max(ipx, 0), WW - 1);
        int cpy = min(max(ipy, 0), HH - 1);
        fidx[m] = cpy * WW + cpx;
    }

    const int c0 = h * CH_PER_T;
    float* vol = out + ((size_t)b * CH + c0) * NVOX + v0;
    const bool anyok = ok[0] | ok[1] | ok[2] | ok[3];

    if (anyok) {
        const float* fb = features + ((size_t)b * CH + c0) * HW;
#pragma unroll
        for (int c = 0; c < CH_PER_T; ++c) {
            const float* fc = fb + (size_t)c * HW;
            float4 o = make_float4(0.f, 0.f, 0.f, 0.f);
            // Predicated loads: invalid lanes issue NO memory request.
            if (ok[0]) o.x = __ldg(fc + fidx[0]);
            if (ok[1]) o.y = __ldg(fc + fidx[1]);
            if (ok[2]) o.z = __ldg(fc + fidx[2]);
            if (ok[3]) o.w = __ldg(fc + fidx[3]);
            __stcs(reinterpret_cast<float4*>(vol + (size_t)c * NVOX), o);
        }
    } else {
        const float4 zero = make_float4(0.f, 0.f, 0.f, 0.f);
#pragma unroll
        for (int c = 0; c < CH_PER_T; ++c)
            __stcs(reinterpret_cast<float4*>(vol + (size_t)c * NVOX), zero);
    }

    if (h == 0) {
        float* vout = out + (size_t)BATCH * CH * NVOX + (size_t)b * NVOX + v0;
        __stcs(reinterpret_cast<float4*>(vout),
               make_float4(ok[0] ? 1.f : 0.f, ok[1] ? 1.f : 0.f,
                           ok[2] ? 1.f : 0.f, ok[3] ? 1.f : 0.f));
    }
}

extern "C" void kernel_launch(void* const* d_in, const int* in_sizes, int n_in,
                              void* d_out, int out_size)
{
    // Expected metadata order: origin[12], projection[48], features[2457600],
    // voxel_size[1]. Identify tensors by unique sizes as a guard.
    const float* origin     = (const float*)d_in[0];
    const float* projection = (const float*)d_in[1];
    const float* features   = (const float*)d_in[2];
    const float* voxel_size = (const float*)d_in[3];
    for (int t = 0; t < n_in; ++t) {
        if (in_sizes[t] == BATCH * CH * HH * WW) features   = (const float*)d_in[t];
        else if (in_sizes[t] == BATCH * 12)      projection = (const float*)d_in[t];
        else if (in_sizes[t] == BATCH * 3)       origin     = (const float*)d_in[t];
    }
    float* out = (float*)d_out;

    const int total_threads = BATCH * CH_SPLIT * (NVOX / 4); // 13,107,200
    const int block = 256;
    const int grid  = (total_threads + block - 1) / block;   // 51200
    backproject_kernel<<<grid, block>>>(origin, projection, features, voxel_size, out);
}